// round 4
// baseline (speedup 1.0000x reference)
#include <cuda_runtime.h>
#include <cuda_bf16.h>
#include <cstdint>

#define D 128
#define MAXN 100000
#define MAXE 600000
#define SCAN_NB ((MAXN + 255) / 256)   // 391

// Scratch (device globals; no allocs allowed)
__device__ float  g_A[(size_t)MAXN * D];   // 51.2 MB
__device__ int    g_count[MAXN];
__device__ int    g_offs[MAXN];
__device__ int    g_cursor[MAXN];
__device__ int    g_bsum[SCAN_NB + 1];
__device__ float2 g_meta[MAXE];            // (.x = src id as float bits, .y = w)

// ---------------------------------------------------------------------------
// Counting sort of edges by dst
// ---------------------------------------------------------------------------
__global__ void zero_count_kernel(int N) {
    int i = blockIdx.x * blockDim.x + threadIdx.x;
    if (i < N) g_count[i] = 0;
}

__global__ void hist_kernel(const int* __restrict__ ei, int E) {
    int e = blockIdx.x * blockDim.x + threadIdx.x;
    if (e < E) atomicAdd(&g_count[ei[E + e]], 1);
}

// s1: per-256-block scan (warp shuffles); exclusive offs + block total
__global__ void scan1_kernel(int N) {
    __shared__ int ws[8];
    int tid = threadIdx.x;
    int lane = tid & 31, wrp = tid >> 5;
    int i = blockIdx.x * 256 + tid;
    int c = (i < N) ? g_count[i] : 0;
    int v = c;
#pragma unroll
    for (int o = 1; o < 32; o <<= 1) {
        int t = __shfl_up_sync(0xffffffffu, v, o);
        if (lane >= o) v += t;
    }
    if (lane == 31) ws[wrp] = v;
    __syncthreads();
    if (wrp == 0) {
        int s = (lane < 8) ? ws[lane] : 0;
#pragma unroll
        for (int o = 1; o < 8; o <<= 1) {
            int t = __shfl_up_sync(0xffffffffu, s, o);
            if (lane >= o) s += t;
        }
        if (lane < 8) ws[lane] = s;
    }
    __syncthreads();
    int incl = v + ((wrp > 0) ? ws[wrp - 1] : 0);
    if (i < N) g_offs[i] = incl - c;
    if (tid == 255) g_bsum[blockIdx.x] = incl;
}

// s2: single block exclusive scan over block sums (shuffles)
__global__ void scan2_kernel(int nb) {
    __shared__ int ws[16];
    int tid = threadIdx.x;
    int lane = tid & 31, wrp = tid >> 5;
    int c = (tid < nb) ? g_bsum[tid] : 0;
    int v = c;
#pragma unroll
    for (int o = 1; o < 32; o <<= 1) {
        int t = __shfl_up_sync(0xffffffffu, v, o);
        if (lane >= o) v += t;
    }
    if (lane == 31) ws[wrp] = v;
    __syncthreads();
    if (wrp == 0) {
        int s = (lane < 16) ? ws[lane] : 0;
#pragma unroll
        for (int o = 1; o < 16; o <<= 1) {
            int t = __shfl_up_sync(0xffffffffu, s, o);
            if (lane >= o) s += t;
        }
        if (lane < 16) ws[lane] = s;
    }
    __syncthreads();
    int incl = v + ((wrp > 0) ? ws[wrp - 1] : 0);
    if (tid < nb) g_bsum[tid] = incl - c;   // exclusive
}

// s3: add block offsets; init cursors
__global__ void scan3_kernel(int N) {
    int i = blockIdx.x * 256 + threadIdx.x;
    if (i < N) {
        int v = g_offs[i] + g_bsum[i >> 8];
        g_offs[i] = v;
        g_cursor[i] = v;
    }
}

// permute: write (src, w) directly into dst-sorted position (no edge-id indirection)
__global__ void permute_kernel(const int* __restrict__ ei,
                               const float* __restrict__ ew, int E) {
    int e = blockIdx.x * blockDim.x + threadIdx.x;
    if (e < E) {
        int dst = ei[E + e];
        int src = ei[e];
        float w = ew[e];
        int pos = atomicAdd(&g_cursor[dst], 1);
        g_meta[pos] = make_float2(__int_as_float(src), w);
    }
}

// ---------------------------------------------------------------------------
// Gather: one warp per dst node. Coalesced lane-parallel metadata load,
// shfl broadcast, 4-deep MLP on row gathers, single plain store of A[d].
// ---------------------------------------------------------------------------
__global__ __launch_bounds__(256) void gather_kernel(
    const float* __restrict__ src_x, int N) {
    int w = (blockIdx.x * 256 + threadIdx.x) >> 5;
    int lane = threadIdx.x & 31;
    if (w >= N) return;
    int base = g_offs[w];
    int deg = g_count[w];
    float4 acc = make_float4(0.f, 0.f, 0.f, 0.f);

    for (int c0 = 0; c0 < deg; c0 += 32) {
        int cn = min(deg - c0, 32);
        float2 mv = make_float2(0.f, 0.f);
        if (lane < cn) mv = __ldg(&g_meta[base + c0 + lane]);
        for (int j = 0; j < cn; j += 4) {
            float4 x[4];
            float wv[4];
#pragma unroll
            for (int u = 0; u < 4; ++u) {
                int idx = j + u;
                int su = __shfl_sync(0xffffffffu, __float_as_int(mv.x), idx & 31);
                float wu = __shfl_sync(0xffffffffu, mv.y, idx & 31);
                bool valid = idx < cn;
                wv[u] = valid ? wu : 0.f;
                if (valid)
                    x[u] = __ldg((const float4*)(src_x + (size_t)su * D) + lane);
                else
                    x[u] = make_float4(0.f, 0.f, 0.f, 0.f);
            }
#pragma unroll
            for (int u = 0; u < 4; ++u) {
                acc.x += wv[u] * x[u].x;
                acc.y += wv[u] * x[u].y;
                acc.z += wv[u] * x[u].z;
                acc.w += wv[u] * x[u].w;
            }
        }
    }
    ((float4*)(g_A + (size_t)w * D))[lane] = acc;
}

// ---------------------------------------------------------------------------
// Fused dual GEMM + leaky_relu on tensor cores (tf32 mma.sync) — unchanged.
//   out = leaky_relu( (dst_x + A) @ Wi^T + (dst_x * A) @ Wn^T )
// ---------------------------------------------------------------------------
#define SSTR 136

__device__ __forceinline__ uint32_t f2tf32(float x) {
    uint32_t r;
    asm("cvt.rna.tf32.f32 %0, %1;" : "=r"(r) : "f"(x));
    return r;
}

__device__ __forceinline__ void mma_tf32(float c[4], const uint32_t a[4],
                                         const uint32_t b[2]) {
    asm volatile(
        "mma.sync.aligned.m16n8k8.row.col.f32.tf32.tf32.f32 "
        "{%0,%1,%2,%3},{%4,%5,%6,%7},{%8,%9},{%0,%1,%2,%3};"
        : "+f"(c[0]), "+f"(c[1]), "+f"(c[2]), "+f"(c[3])
        : "r"(a[0]), "r"(a[1]), "r"(a[2]), "r"(a[3]), "r"(b[0]), "r"(b[1]));
}

__global__ __launch_bounds__(256) void fused_gemm_tc_kernel(
    const float* __restrict__ dstx,
    const float* __restrict__ Wi,
    const float* __restrict__ Wn,
    float* __restrict__ out, int N) {

    __shared__ uint32_t u_s[16][SSTR];
    __shared__ uint32_t v_s[16][SSTR];
    __shared__ uint32_t wi_s[16][SSTR];
    __shared__ uint32_t wn_s[16][SSTR];

    const int tid = threadIdx.x;
    const int lane = tid & 31;
    const int wid = tid >> 5;
    const int wm = wid >> 2;
    const int wn = wid & 3;
    const int grp = lane >> 2;
    const int qid = lane & 3;
    const int row0 = blockIdx.x * 128;

    const int fm = tid >> 1;
    const int fkq = (tid & 1) * 8;

    float acc[4][4][4];
#pragma unroll
    for (int mt = 0; mt < 4; ++mt)
#pragma unroll
        for (int nt = 0; nt < 4; ++nt)
#pragma unroll
            for (int c = 0; c < 4; ++c) acc[mt][nt][c] = 0.f;

    for (int kt = 0; kt < 8; ++kt) {
        const int k0 = kt * 16;
        {
            int row = row0 + fm;
            float4 d0 = make_float4(0.f, 0.f, 0.f, 0.f), d1 = d0;
            float4 a0 = d0, a1 = d0;
            if (row < N) {
                const float4* dp = (const float4*)(dstx + (size_t)row * D + k0 + fkq);
                const float4* ap = (const float4*)(g_A + (size_t)row * D + k0 + fkq);
                d0 = dp[0]; d1 = dp[1];
                a0 = ap[0]; a1 = ap[1];
            }
            float du[8] = {d0.x, d0.y, d0.z, d0.w, d1.x, d1.y, d1.z, d1.w};
            float au[8] = {a0.x, a0.y, a0.z, a0.w, a1.x, a1.y, a1.z, a1.w};
#pragma unroll
            for (int j = 0; j < 8; ++j) {
                u_s[fkq + j][fm] = f2tf32(du[j] + au[j]);
                v_s[fkq + j][fm] = f2tf32(du[j] * au[j]);
            }
            const float4* wip = (const float4*)(Wi + fm * D + k0 + fkq);
            const float4* wnp = (const float4*)(Wn + fm * D + k0 + fkq);
            float4 wi0 = wip[0], wi1 = wip[1];
            float4 wn0 = wnp[0], wn1 = wnp[1];
            float wif[8] = {wi0.x, wi0.y, wi0.z, wi0.w, wi1.x, wi1.y, wi1.z, wi1.w};
            float wnf[8] = {wn0.x, wn0.y, wn0.z, wn0.w, wn1.x, wn1.y, wn1.z, wn1.w};
#pragma unroll
            for (int j = 0; j < 8; ++j) {
                wi_s[fkq + j][fm] = f2tf32(wif[j]);
                wn_s[fkq + j][fm] = f2tf32(wnf[j]);
            }
        }
        __syncthreads();

#pragma unroll
        for (int ph = 0; ph < 2; ++ph) {
            const uint32_t(*S)[SSTR] = ph ? v_s : u_s;
            const uint32_t(*W)[SSTR] = ph ? wn_s : wi_s;
#pragma unroll
            for (int kk = 0; kk < 16; kk += 8) {
                uint32_t af[4][4];
#pragma unroll
                for (int mt = 0; mt < 4; ++mt) {
                    int mr = wm * 64 + mt * 16 + grp;
                    af[mt][0] = S[kk + qid][mr];
                    af[mt][1] = S[kk + qid][mr + 8];
                    af[mt][2] = S[kk + qid + 4][mr];
                    af[mt][3] = S[kk + qid + 4][mr + 8];
                }
                uint32_t bf[4][2];
#pragma unroll
                for (int nt = 0; nt < 4; ++nt) {
                    int nc = wn * 32 + nt * 8 + grp;
                    bf[nt][0] = W[kk + qid][nc];
                    bf[nt][1] = W[kk + qid + 4][nc];
                }
#pragma unroll
                for (int mt = 0; mt < 4; ++mt)
#pragma unroll
                    for (int nt = 0; nt < 4; ++nt)
                        mma_tf32(acc[mt][nt], af[mt], bf[nt]);
            }
        }
        __syncthreads();
    }

#pragma unroll
    for (int mt = 0; mt < 4; ++mt) {
#pragma unroll
        for (int nt = 0; nt < 4; ++nt) {
            int col = wn * 32 + nt * 8 + qid * 2;
            int r0 = row0 + wm * 64 + mt * 16 + grp;
            int r1 = r0 + 8;
            float x0 = acc[mt][nt][0], x1 = acc[mt][nt][1];
            float x2 = acc[mt][nt][2], x3 = acc[mt][nt][3];
            x0 = x0 > 0.f ? x0 : 0.01f * x0;
            x1 = x1 > 0.f ? x1 : 0.01f * x1;
            x2 = x2 > 0.f ? x2 : 0.01f * x2;
            x3 = x3 > 0.f ? x3 : 0.01f * x3;
            if (r0 < N)
                *(float2*)(out + (size_t)r0 * D + col) = make_float2(x0, x1);
            if (r1 < N)
                *(float2*)(out + (size_t)r1 * D + col) = make_float2(x2, x3);
        }
    }
}

// ---------------------------------------------------------------------------
extern "C" void kernel_launch(void* const* d_in, const int* in_sizes, int n_in,
                              void* d_out, int out_size) {
    const float* src_x = (const float*)d_in[0];
    const float* dst_x = (const float*)d_in[1];
    const int*   ei    = (const int*)d_in[2];    // [2, E]
    const float* ew    = (const float*)d_in[3];  // [E]
    const float* Wi    = (const float*)d_in[4];
    const float* Wn    = (const float*)d_in[5];
    float* out = (float*)d_out;

    int N = in_sizes[0] / D;
    int E = in_sizes[2] / 2;
    int nb = (N + 255) / 256;

    zero_count_kernel<<<nb, 256>>>(N);
    hist_kernel<<<(E + 255) / 256, 256>>>(ei, E);
    scan1_kernel<<<nb, 256>>>(N);
    scan2_kernel<<<1, 512>>>(nb);
    scan3_kernel<<<nb, 256>>>(N);
    permute_kernel<<<(E + 255) / 256, 256>>>(ei, ew, E);
    gather_kernel<<<(N * 32 + 255) / 256, 256>>>(src_x, N);
    fused_gemm_tc_kernel<<<(N + 127) / 128, 256>>>(dst_x, Wi, Wn, out, N);
}